// round 9
// baseline (speedup 1.0000x reference)
#include <cuda_runtime.h>
#include <cstdint>

#define NB 2
#define NT 2048
#define ND 1024
#define NH 16
#define NDK 64

// Scratch (allocation-free). __align__(16): float4 access requires 16B alignment.
__device__ __align__(16) float g_q[NB * NH * NT * NDK];
__device__ __align__(16) float g_k[NB * NH * NT * NDK];
__device__ __align__(16) float g_v[NB * NH * NT * NDK];
__device__ __align__(16) float g_ctx[NB * NT * ND];

// ---------------------------------------------------------------------------
// SGEMM: C = A[4096,1024] @ W[1024,1024]^T + bias[1024]
// sel 0/1/2 -> write g_q/g_k/g_v in split-head [B,H,T,DK] layout
// sel 3     -> A = g_ctx, write Cout (d_out) in [B,T,D] layout
// Tile 128x128x16, 256 threads, 8x8 per-thread microtile. Static smem only.
// ---------------------------------------------------------------------------
__global__ __launch_bounds__(256) void sgemm_kernel(
    const float* __restrict__ A_, const float* __restrict__ W,
    const float* __restrict__ bias, float* __restrict__ Cout, int sel)
{
    __shared__ float As[16][132];
    __shared__ float Bs[16][132];

    const float* A = (sel == 3) ? g_ctx : A_;
    float* C = (sel == 0) ? g_q : (sel == 1) ? g_k : (sel == 2) ? g_v : Cout;

    const int tid = threadIdx.x;
    const int tx = tid & 15;
    const int ty = tid >> 4;
    const int m0 = blockIdx.y * 128;
    const int n0 = blockIdx.x * 128;

    float acc[8][8];
#pragma unroll
    for (int i = 0; i < 8; i++)
#pragma unroll
        for (int j = 0; j < 8; j++) acc[i][j] = 0.0f;

    for (int k0 = 0; k0 < 1024; k0 += 16) {
#pragma unroll
        for (int s = 0; s < 2; s++) {
            int f = tid + s * 256;
            int row = f >> 2;
            int kc = (f & 3) << 2;
            float4 va = *(const float4*)(A + (size_t)(m0 + row) * 1024 + k0 + kc);
            As[kc + 0][row] = va.x; As[kc + 1][row] = va.y;
            As[kc + 2][row] = va.z; As[kc + 3][row] = va.w;
            float4 vb = *(const float4*)(W + (size_t)(n0 + row) * 1024 + k0 + kc);
            Bs[kc + 0][row] = vb.x; Bs[kc + 1][row] = vb.y;
            Bs[kc + 2][row] = vb.z; Bs[kc + 3][row] = vb.w;
        }
        __syncthreads();

#pragma unroll
        for (int kk = 0; kk < 16; kk++) {
            float a[8], b[8];
            *(float4*)&a[0] = *(const float4*)&As[kk][ty * 4];
            *(float4*)&a[4] = *(const float4*)&As[kk][64 + ty * 4];
            *(float4*)&b[0] = *(const float4*)&Bs[kk][tx * 4];
            *(float4*)&b[4] = *(const float4*)&Bs[kk][64 + tx * 4];
#pragma unroll
            for (int i = 0; i < 8; i++)
#pragma unroll
                for (int j = 0; j < 8; j++)
                    acc[i][j] += a[i] * b[j];
        }
        __syncthreads();
    }

#pragma unroll
    for (int ih = 0; ih < 2; ih++)
#pragma unroll
        for (int i = 0; i < 4; i++) {
            int row = m0 + ih * 64 + ty * 4 + i;
#pragma unroll
            for (int jh = 0; jh < 2; jh++) {
                int col = n0 + jh * 64 + tx * 4;
                float4 v;
                v.x = acc[ih * 4 + i][jh * 4 + 0] + bias[col + 0];
                v.y = acc[ih * 4 + i][jh * 4 + 1] + bias[col + 1];
                v.z = acc[ih * 4 + i][jh * 4 + 2] + bias[col + 2];
                v.w = acc[ih * 4 + i][jh * 4 + 3] + bias[col + 3];
                if (sel < 3) {
                    int bb = row >> 11;       // / 2048
                    int t  = row & 2047;
                    int h  = col >> 6;        // head (4-col chunk never crosses head)
                    int dk = col & 63;
                    *(float4*)(C + ((((size_t)(bb * NH + h)) * NT + t) << 6) + dk) = v;
                } else {
                    *(float4*)(C + (size_t)row * 1024 + col) = v;
                }
            }
        }
}

// ---------------------------------------------------------------------------
// Flash attention, fp32. Grid (32 qtiles, 16 heads, 2 batch), 256 threads.
// 64-query tile; streams 32-key tiles; online softmax; writes ctx [B,T,D].
// All-static shared memory (~44.7 KB < 48 KB) -> no cudaFuncSetAttribute.
// Thread map: tx = tid&7 (keys: 4 each / d-cols: 8 each), ty = tid>>3 (2 q-rows).
// ---------------------------------------------------------------------------
#define KT    32
#define PADQ  68   // Qs row width (i-dim 64 + 4)
#define PADK  36   // Ks/Ps row width (j-dim 32 + 4)
#define PADV  68   // Vs row width (d-dim 64 + 4)

__global__ __launch_bounds__(256) void attn_kernel(const int* __restrict__ mask)
{
    __shared__ float Qs[64 * PADQ];   // transposed: Qs[d*PADQ + i]
    __shared__ float Ks[64 * PADK];   // transposed: Ks[d*PADK + j]
    __shared__ float Vs[KT * PADV];   // natural:    Vs[j*PADV + d]
    __shared__ float Ps[64 * PADK];   // Ps[i*PADK + j]
    __shared__ float maskb[KT];

    const int tid = threadIdx.x;
    const int tx = tid & 7;
    const int ty = tid >> 3;
    const int q0 = blockIdx.x * 64;
    const int h = blockIdx.y;
    const int b = blockIdx.z;

    const float* Qh = g_q + (size_t)(b * NH + h) * NT * NDK;
    const float* Kh = g_k + (size_t)(b * NH + h) * NT * NDK;
    const float* Vh = g_v + (size_t)(b * NH + h) * NT * NDK;
    const int* mrow = mask + b * NT;

    // Load Q tile transposed (64 queries x 64 d)
#pragma unroll
    for (int s = 0; s < 4; s++) {
        int f = tid + s * 256;
        int i = f >> 4;
        int dc = (f & 15) << 2;
        float4 v = *(const float4*)(Qh + (size_t)(q0 + i) * 64 + dc);
        Qs[(dc + 0) * PADQ + i] = v.x; Qs[(dc + 1) * PADQ + i] = v.y;
        Qs[(dc + 2) * PADQ + i] = v.z; Qs[(dc + 3) * PADQ + i] = v.w;
    }
    // (first __syncthreads_or below orders these writes before any read)

    float m[2], l[2], o[2][8];
#pragma unroll
    for (int r = 0; r < 2; r++) {
        m[r] = -1e30f;
        l[r] = 0.0f;
#pragma unroll
        for (int c = 0; c < 8; c++) o[r][c] = 0.0f;
    }

    for (int k0 = 0; k0 < NT; k0 += KT) {
        int pred = 0;
        if (tid < KT) {
            int mv = mrow[k0 + tid];
            maskb[tid] = mv ? 0.0f : -1e30f;
            pred = mv;
        }
        if (!__syncthreads_or(pred)) continue;   // whole key tile padded -> skip

        // Load K (transposed) and V (natural): 32 keys x 64 d = 512 float4
#pragma unroll
        for (int s = 0; s < 2; s++) {
            int f = tid + s * 256;
            int j = f >> 4;
            int dc = (f & 15) << 2;
            float4 kv = *(const float4*)(Kh + (size_t)(k0 + j) * 64 + dc);
            Ks[(dc + 0) * PADK + j] = kv.x; Ks[(dc + 1) * PADK + j] = kv.y;
            Ks[(dc + 2) * PADK + j] = kv.z; Ks[(dc + 3) * PADK + j] = kv.w;
            float4 vv = *(const float4*)(Vh + (size_t)(k0 + j) * 64 + dc);
            *(float4*)(Vs + j * PADV + dc) = vv;
        }
        __syncthreads();

        // S = Q @ K^T   (2 q-rows x 4 k-cols per thread)
        float s4[2][4];
#pragma unroll
        for (int r = 0; r < 2; r++)
#pragma unroll
            for (int c = 0; c < 4; c++) s4[r][c] = 0.0f;

#pragma unroll
        for (int d = 0; d < 64; d++) {
            float a[2], kb[4];
            *(float2*)a  = *(const float2*)(Qs + d * PADQ + ty * 2);
            *(float4*)kb = *(const float4*)(Ks + d * PADK + tx * 4);
#pragma unroll
            for (int r = 0; r < 2; r++)
#pragma unroll
                for (int c = 0; c < 4; c++)
                    s4[r][c] += a[r] * kb[c];
        }

        float mb[4];
        *(float4*)mb = *(const float4*)(maskb + tx * 4);
#pragma unroll
        for (int r = 0; r < 2; r++)
#pragma unroll
            for (int c = 0; c < 4; c++)
                s4[r][c] = s4[r][c] * 0.125f + mb[c];   // DK^-0.5 = 0.125

        // Online softmax: reduce over the 8 tx lanes (xor offsets 4,2,1)
#pragma unroll
        for (int r = 0; r < 2; r++) {
            float rm = fmaxf(fmaxf(s4[r][0], s4[r][1]), fmaxf(s4[r][2], s4[r][3]));
#pragma unroll
            for (int off = 4; off; off >>= 1)
                rm = fmaxf(rm, __shfl_xor_sync(0xffffffffu, rm, off));
            float mn = fmaxf(m[r], rm);
            float fac = __expf(m[r] - mn);
            float rs = 0.0f;
#pragma unroll
            for (int c = 0; c < 4; c++) {
                float p = __expf(s4[r][c] - mn);
                s4[r][c] = p;
                rs += p;
            }
#pragma unroll
            for (int off = 4; off; off >>= 1)
                rs += __shfl_xor_sync(0xffffffffu, rs, off);
            l[r] = l[r] * fac + rs;
            m[r] = mn;
#pragma unroll
            for (int c = 0; c < 8; c++) o[r][c] *= fac;
        }

        // Stage P tile
#pragma unroll
        for (int r = 0; r < 2; r++) {
            float4 pv = { s4[r][0], s4[r][1], s4[r][2], s4[r][3] };
            *(float4*)(Ps + (ty * 2 + r) * PADK + tx * 4) = pv;
        }
        __syncthreads();

        // O += P @ V   (2 q-rows x 8 d-cols per thread)
#pragma unroll
        for (int kk = 0; kk < KT; kk++) {
            float vb[8];
            *(float4*)&vb[0] = *(const float4*)(Vs + kk * PADV + tx * 8);
            *(float4*)&vb[4] = *(const float4*)(Vs + kk * PADV + tx * 8 + 4);
#pragma unroll
            for (int r = 0; r < 2; r++) {
                float a = Ps[(ty * 2 + r) * PADK + kk];
#pragma unroll
                for (int c = 0; c < 8; c++)
                    o[r][c] += a * vb[c];
            }
        }
        __syncthreads();
    }

    // Epilogue: ctx[b, t, h*64 + dk] = O / l
    float* ctxb = g_ctx + (size_t)b * NT * ND;
#pragma unroll
    for (int r = 0; r < 2; r++) {
        float inv = 1.0f / l[r];
        int t = q0 + ty * 2 + r;
        float4 v0 = { o[r][0] * inv, o[r][1] * inv, o[r][2] * inv, o[r][3] * inv };
        float4 v1 = { o[r][4] * inv, o[r][5] * inv, o[r][6] * inv, o[r][7] * inv };
        *(float4*)(ctxb + (size_t)t * ND + h * 64 + tx * 8)     = v0;
        *(float4*)(ctxb + (size_t)t * ND + h * 64 + tx * 8 + 4) = v1;
    }
}

// ---------------------------------------------------------------------------
// kernel_launch: ONLY kernel launches on the default stream. No other CUDA
// API calls (no attribute sets, no memcpy, no allocation) -> trivially
// graph-capturable.
// ---------------------------------------------------------------------------
extern "C" void kernel_launch(void* const* d_in, const int* in_sizes, int n_in,
                              void* d_out, int out_size)
{
    const float* q    = (const float*)d_in[0];
    const float* k    = (const float*)d_in[1];
    const float* v    = (const float*)d_in[2];
    const int*   mask = (const int*)d_in[3];
    const float* Wq   = (const float*)d_in[4];
    const float* bq   = (const float*)d_in[5];
    const float* Wk   = (const float*)d_in[6];
    const float* bk   = (const float*)d_in[7];
    const float* Wv   = (const float*)d_in[8];
    const float* bv   = (const float*)d_in[9];
    const float* Wo   = (const float*)d_in[10];
    const float* bo   = (const float*)d_in[11];
    float* out = (float*)d_out;

    dim3 gg(8, 32);  // N tiles x M tiles (128x128 over 4096x1024)
    sgemm_kernel<<<gg, 256>>>(q, Wq, bq, nullptr, 0);
    sgemm_kernel<<<gg, 256>>>(k, Wk, bk, nullptr, 1);
    sgemm_kernel<<<gg, 256>>>(v, Wv, bv, nullptr, 2);
    attn_kernel<<<dim3(32, 16, 2), 256>>>(mask);
    sgemm_kernel<<<gg, 256>>>(nullptr, Wo, bo, out, 3);
}

// round 10
// speedup vs baseline: 1.2087x; 1.2087x over previous
#include <cuda_runtime.h>
#include <cuda_bf16.h>
#include <cstdint>

#define NB 2
#define NT 2048
#define ND 1024
#define NH 16
#define NDK 64

// Scratch (allocation-free). __align__(16): float4 access requires 16B alignment.
__device__ __align__(16) float g_q[NB * NH * NT * NDK];
__device__ __align__(16) float g_k[NB * NH * NT * NDK];
__device__ __align__(16) float g_v[NB * NH * NT * NDK];
__device__ __align__(16) float g_ctx[NB * NT * ND];

// ---------------------------------------------------------------------------
// Tensor-core GEMM with bf16 split precision (bf16x3):
//   x = hi + lo (hi = bf16(x), lo = bf16(x - hi))
//   A@B ~= Ah@Bh + Ah@Bl + Al@Bh   (lo*lo term ~2^-16, dropped)
// C = A[4096,1024] @ W[1024,1024]^T + bias, fp32 accumulate.
// sel 0/1/2 -> scatter into g_q/g_k/g_v [B,H,T,DK]; sel 3 -> A=g_ctx, C=d_out.
// CTA tile 128x128, 8 warps (2M x 4N), warp tile 64x32, k-chunk 16.
// ---------------------------------------------------------------------------
#define LDAB 24   // smem row stride in bf16 (48B: 16B-aligned rows, conflict-free ldmatrix)

__device__ __forceinline__ void ldsm4(uint32_t* r, uint32_t addr) {
    asm volatile("ldmatrix.sync.aligned.m8n8.x4.shared.b16 {%0,%1,%2,%3}, [%4];"
        : "=r"(r[0]), "=r"(r[1]), "=r"(r[2]), "=r"(r[3]) : "r"(addr));
}

__device__ __forceinline__ void mma16816(float* c, const uint32_t* a, uint32_t b0, uint32_t b1) {
    asm volatile("mma.sync.aligned.m16n8k16.row.col.f32.bf16.bf16.f32 "
        "{%0,%1,%2,%3}, {%4,%5,%6,%7}, {%8,%9}, {%0,%1,%2,%3};"
        : "+f"(c[0]), "+f"(c[1]), "+f"(c[2]), "+f"(c[3])
        : "r"(a[0]), "r"(a[1]), "r"(a[2]), "r"(a[3]), "r"(b0), "r"(b1));
}

__device__ __forceinline__ void split_store(__nv_bfloat16* hi, __nv_bfloat16* lo,
                                            int idx, float x, float y) {
    __nv_bfloat16 hx = __float2bfloat16(x);
    __nv_bfloat16 hy = __float2bfloat16(y);
    __nv_bfloat16 lx = __float2bfloat16(x - __bfloat162float(hx));
    __nv_bfloat16 ly = __float2bfloat16(y - __bfloat162float(hy));
    *(__nv_bfloat162*)(hi + idx) = __nv_bfloat162(hx, hy);
    *(__nv_bfloat162*)(lo + idx) = __nv_bfloat162(lx, ly);
}

__global__ __launch_bounds__(256) void gemm_bf3_kernel(
    const float* __restrict__ A_, const float* __restrict__ W,
    const float* __restrict__ bias, float* __restrict__ Cout, int sel)
{
    __shared__ __align__(16) __nv_bfloat16 Ah[128 * LDAB];
    __shared__ __align__(16) __nv_bfloat16 Al[128 * LDAB];
    __shared__ __align__(16) __nv_bfloat16 Bh[128 * LDAB];
    __shared__ __align__(16) __nv_bfloat16 Bl[128 * LDAB];

    const float* A = (sel == 3) ? g_ctx : A_;
    float* C = (sel == 0) ? g_q : (sel == 1) ? g_k : (sel == 2) ? g_v : Cout;

    const int tid = threadIdx.x;
    const int lane = tid & 31;
    const int warp = tid >> 5;
    const int wm = (warp >> 2) * 64;   // warp M offset (0/64)
    const int wn = (warp & 3) * 32;    // warp N offset (0/32/64/96)
    const int m0 = blockIdx.y * 128;
    const int n0 = blockIdx.x * 128;

    // Loader mapping: f in [0,512): row=f>>2 (0..127), kc=(f&3)*4
    const int lrow0 = tid >> 2;
    const int lkc = (tid & 3) << 2;

    // ldmatrix source addresses (loop-invariant: smem tile reused every chunk)
    const int lr = lane & 15;
    const int lc = (lane >> 4) * 8;
    uint32_t aAdH[4], aAdL[4], bAdH[2], bAdL[2];
#pragma unroll
    for (int i = 0; i < 4; i++) {
        int r = (wm + i * 16 + lr) * LDAB + lc;
        aAdH[i] = (uint32_t)__cvta_generic_to_shared(&Ah[r]);
        aAdL[i] = (uint32_t)__cvta_generic_to_shared(&Al[r]);
    }
#pragma unroll
    for (int j = 0; j < 2; j++) {
        int r = (wn + j * 16 + lr) * LDAB + lc;
        bAdH[j] = (uint32_t)__cvta_generic_to_shared(&Bh[r]);
        bAdL[j] = (uint32_t)__cvta_generic_to_shared(&Bl[r]);
    }

    float acc[4][4][4];
#pragma unroll
    for (int i = 0; i < 4; i++)
#pragma unroll
        for (int j = 0; j < 4; j++)
#pragma unroll
            for (int e = 0; e < 4; e++) acc[i][j][e] = 0.0f;

    // Prefetch chunk 0
    float4 pa[2], pb[2];
#pragma unroll
    for (int s = 0; s < 2; s++) {
        int row = lrow0 + s * 64;
        pa[s] = *(const float4*)(A + (size_t)(m0 + row) * 1024 + lkc);
        pb[s] = *(const float4*)(W + (size_t)(n0 + row) * 1024 + lkc);
    }

    for (int k0 = 0; k0 < 1024; k0 += 16) {
        // Store current chunk (fp32 -> bf16 hi/lo)
#pragma unroll
        for (int s = 0; s < 2; s++) {
            int row = lrow0 + s * 64;
            int idx = row * LDAB + lkc;
            split_store(Ah, Al, idx,     pa[s].x, pa[s].y);
            split_store(Ah, Al, idx + 2, pa[s].z, pa[s].w);
            split_store(Bh, Bl, idx,     pb[s].x, pb[s].y);
            split_store(Bh, Bl, idx + 2, pb[s].z, pb[s].w);
        }
        __syncthreads();

        // Prefetch next chunk (LDG latency overlaps the MMA phase)
        if (k0 + 16 < 1024) {
#pragma unroll
            for (int s = 0; s < 2; s++) {
                int row = lrow0 + s * 64;
                pa[s] = *(const float4*)(A + (size_t)(m0 + row) * 1024 + k0 + 16 + lkc);
                pb[s] = *(const float4*)(W + (size_t)(n0 + row) * 1024 + k0 + 16 + lkc);
            }
        }

        // Load fragments
        uint32_t ah[4][4], al[4][4], bh[2][4], bl[2][4];
#pragma unroll
        for (int i = 0; i < 4; i++) { ldsm4(ah[i], aAdH[i]); ldsm4(al[i], aAdL[i]); }
#pragma unroll
        for (int j = 0; j < 2; j++) { ldsm4(bh[j], bAdH[j]); ldsm4(bl[j], bAdL[j]); }

        // 4m x 4n x 3 terms
#pragma unroll
        for (int i = 0; i < 4; i++)
#pragma unroll
            for (int jb = 0; jb < 2; jb++)
#pragma unroll
                for (int jn = 0; jn < 2; jn++) {
                    float* c = acc[i][jb * 2 + jn];
                    mma16816(c, ah[i], bh[jb][jn], bh[jb][jn + 2]);   // hi*hi
                    mma16816(c, ah[i], bl[jb][jn], bl[jb][jn + 2]);   // hi*lo
                    mma16816(c, al[i], bh[jb][jn], bh[jb][jn + 2]);   // lo*hi
                }
        __syncthreads();
    }

    // Epilogue: bias + scatter. Frag element map: (row = lane/4 [+8], col = (lane%4)*2 +{0,1})
    const int er = lane >> 2;
    const int ec = (lane & 3) * 2;
#pragma unroll
    for (int i = 0; i < 4; i++) {
        int rowA = m0 + wm + i * 16 + er;
#pragma unroll
        for (int j = 0; j < 4; j++) {
            int col = n0 + wn + j * 8 + ec;
            float bx = bias[col];
            float by = bias[col + 1];
#pragma unroll
            for (int half = 0; half < 2; half++) {
                int row = rowA + half * 8;
                float2 v;
                v.x = acc[i][j][half * 2 + 0] + bx;
                v.y = acc[i][j][half * 2 + 1] + by;
                if (sel < 3) {
                    int bb = row >> 11;
                    int t  = row & 2047;
                    int h  = col >> 6;
                    int dk = col & 63;
                    *(float2*)(C + ((((size_t)(bb * NH + h)) * NT + t) << 6) + dk) = v;
                } else {
                    *(float2*)(C + (size_t)row * 1024 + col) = v;
                }
            }
        }
    }
}

// ---------------------------------------------------------------------------
// Flash attention, fp32 (unchanged from passing R9 version).
// Grid (32 qtiles, 16 heads, 2 batch), 256 threads, 32-key tiles, static smem.
// ---------------------------------------------------------------------------
#define KT    32
#define PADQ  68
#define PADK  36
#define PADV  68

__global__ __launch_bounds__(256) void attn_kernel(const int* __restrict__ mask)
{
    __shared__ float Qs[64 * PADQ];
    __shared__ float Ks[64 * PADK];
    __shared__ float Vs[KT * PADV];
    __shared__ float Ps[64 * PADK];
    __shared__ float maskb[KT];

    const int tid = threadIdx.x;
    const int tx = tid & 7;
    const int ty = tid >> 3;
    const int q0 = blockIdx.x * 64;
    const int h = blockIdx.y;
    const int b = blockIdx.z;

    const float* Qh = g_q + (size_t)(b * NH + h) * NT * NDK;
    const float* Kh = g_k + (size_t)(b * NH + h) * NT * NDK;
    const float* Vh = g_v + (size_t)(b * NH + h) * NT * NDK;
    const int* mrow = mask + b * NT;

#pragma unroll
    for (int s = 0; s < 4; s++) {
        int f = tid + s * 256;
        int i = f >> 4;
        int dc = (f & 15) << 2;
        float4 v = *(const float4*)(Qh + (size_t)(q0 + i) * 64 + dc);
        Qs[(dc + 0) * PADQ + i] = v.x; Qs[(dc + 1) * PADQ + i] = v.y;
        Qs[(dc + 2) * PADQ + i] = v.z; Qs[(dc + 3) * PADQ + i] = v.w;
    }

    float m[2], l[2], o[2][8];
#pragma unroll
    for (int r = 0; r < 2; r++) {
        m[r] = -1e30f;
        l[r] = 0.0f;
#pragma unroll
        for (int c = 0; c < 8; c++) o[r][c] = 0.0f;
    }

    for (int k0 = 0; k0 < NT; k0 += KT) {
        int pred = 0;
        if (tid < KT) {
            int mv = mrow[k0 + tid];
            maskb[tid] = mv ? 0.0f : -1e30f;
            pred = mv;
        }
        if (!__syncthreads_or(pred)) continue;

#pragma unroll
        for (int s = 0; s < 2; s++) {
            int f = tid + s * 256;
            int j = f >> 4;
            int dc = (f & 15) << 2;
            float4 kv = *(const float4*)(Kh + (size_t)(k0 + j) * 64 + dc);
            Ks[(dc + 0) * PADK + j] = kv.x; Ks[(dc + 1) * PADK + j] = kv.y;
            Ks[(dc + 2) * PADK + j] = kv.z; Ks[(dc + 3) * PADK + j] = kv.w;
            float4 vv = *(const float4*)(Vh + (size_t)(k0 + j) * 64 + dc);
            *(float4*)(Vs + j * PADV + dc) = vv;
        }
        __syncthreads();

        float s4[2][4];
#pragma unroll
        for (int r = 0; r < 2; r++)
#pragma unroll
            for (int c = 0; c < 4; c++) s4[r][c] = 0.0f;

#pragma unroll
        for (int d = 0; d < 64; d++) {
            float a[2], kb[4];
            *(float2*)a  = *(const float2*)(Qs + d * PADQ + ty * 2);
            *(float4*)kb = *(const float4*)(Ks + d * PADK + tx * 4);
#pragma unroll
            for (int r = 0; r < 2; r++)
#pragma unroll
                for (int c = 0; c < 4; c++)
                    s4[r][c] += a[r] * kb[c];
        }

        float mb[4];
        *(float4*)mb = *(const float4*)(maskb + tx * 4);
#pragma unroll
        for (int r = 0; r < 2; r++)
#pragma unroll
            for (int c = 0; c < 4; c++)
                s4[r][c] = s4[r][c] * 0.125f + mb[c];

#pragma unroll
        for (int r = 0; r < 2; r++) {
            float rm = fmaxf(fmaxf(s4[r][0], s4[r][1]), fmaxf(s4[r][2], s4[r][3]));
#pragma unroll
            for (int off = 4; off; off >>= 1)
                rm = fmaxf(rm, __shfl_xor_sync(0xffffffffu, rm, off));
            float mn = fmaxf(m[r], rm);
            float fac = __expf(m[r] - mn);
            float rs = 0.0f;
#pragma unroll
            for (int c = 0; c < 4; c++) {
                float p = __expf(s4[r][c] - mn);
                s4[r][c] = p;
                rs += p;
            }
#pragma unroll
            for (int off = 4; off; off >>= 1)
                rs += __shfl_xor_sync(0xffffffffu, rs, off);
            l[r] = l[r] * fac + rs;
            m[r] = mn;
#pragma unroll
            for (int c = 0; c < 8; c++) o[r][c] *= fac;
        }

#pragma unroll
        for (int r = 0; r < 2; r++) {
            float4 pv = { s4[r][0], s4[r][1], s4[r][2], s4[r][3] };
            *(float4*)(Ps + (ty * 2 + r) * PADK + tx * 4) = pv;
        }
        __syncthreads();

#pragma unroll
        for (int kk = 0; kk < KT; kk++) {
            float vb[8];
            *(float4*)&vb[0] = *(const float4*)(Vs + kk * PADV + tx * 8);
            *(float4*)&vb[4] = *(const float4*)(Vs + kk * PADV + tx * 8 + 4);
#pragma unroll
            for (int r = 0; r < 2; r++) {
                float a = Ps[(ty * 2 + r) * PADK + kk];
#pragma unroll
                for (int c = 0; c < 8; c++)
                    o[r][c] += a * vb[c];
            }
        }
        __syncthreads();
    }

    float* ctxb = g_ctx + (size_t)b * NT * ND;
#pragma unroll
    for (int r = 0; r < 2; r++) {
        float inv = 1.0f / l[r];
        int t = q0 + ty * 2 + r;
        float4 v0 = { o[r][0] * inv, o[r][1] * inv, o[r][2] * inv, o[r][3] * inv };
        float4 v1 = { o[r][4] * inv, o[r][5] * inv, o[r][6] * inv, o[r][7] * inv };
        *(float4*)(ctxb + (size_t)t * ND + h * 64 + tx * 8)     = v0;
        *(float4*)(ctxb + (size_t)t * ND + h * 64 + tx * 8 + 4) = v1;
    }
}

// ---------------------------------------------------------------------------
// kernel_launch: only kernel launches on the default stream.
// ---------------------------------------------------------------------------
extern "C" void kernel_launch(void* const* d_in, const int* in_sizes, int n_in,
                              void* d_out, int out_size)
{
    const float* q    = (const float*)d_in[0];
    const float* k    = (const float*)d_in[1];
    const float* v    = (const float*)d_in[2];
    const int*   mask = (const int*)d_in[3];
    const float* Wq   = (const float*)d_in[4];
    const float* bq   = (const float*)d_in[5];
    const float* Wk   = (const float*)d_in[6];
    const float* bk   = (const float*)d_in[7];
    const float* Wv   = (const float*)d_in[8];
    const float* bv   = (const float*)d_in[9];
    const float* Wo   = (const float*)d_in[10];
    const float* bo   = (const float*)d_in[11];
    float* out = (float*)d_out;

    dim3 gg(8, 32);  // N tiles x M tiles (128x128 over 4096x1024)
    gemm_bf3_kernel<<<gg, 256>>>(q, Wq, bq, nullptr, 0);
    gemm_bf3_kernel<<<gg, 256>>>(k, Wk, bk, nullptr, 1);
    gemm_bf3_kernel<<<gg, 256>>>(v, Wv, bv, nullptr, 2);
    attn_kernel<<<dim3(32, 16, 2), 256>>>(mask);
    gemm_bf3_kernel<<<gg, 256>>>(nullptr, Wo, bo, out, 3);
}